// round 12
// baseline (speedup 1.0000x reference)
#include <cuda_runtime.h>
#include <cuda_bf16.h>
#include <cuda_fp16.h>
#include <math.h>
#include <stdint.h>

#define B 16
#define S 1024
#define H 256
#define NH 4
#define DH 64
#define H2 128
#define MROWS (B*S)   // 16384
#define CEXP (0.125f * 1.44269504f)

// ---------------- scratch (static device globals) ----------------
__device__ __align__(16) __nv_bfloat16 g_xh[MROWS*H];
__device__ __align__(16) __nv_bfloat16 g_WqkT[512*H];                    // [Wq|Wk]^T
__device__ __align__(16) __nv_bfloat16 g_WmiT[384*H];                    // [Wm1|Wi1]^T
__device__ __align__(16) __nv_bfloat16 g_Wi2T[H*H];
__device__ __align__(16) __nv_bfloat16 g_We1T[H2*H];
__device__ __align__(16) __nv_bfloat16 g_qkh[MROWS*512];                 // packed q|k bf16 (q pre-scaled)
__device__ __align__(16) __nv_bfloat16 g_i1b[MROWS*H];
__device__ __align__(16) __nv_bfloat16 g_fb[MROWS*H];
__device__ float g_str[B*S];
__device__ float g_awsum[B*S];
__device__ float g_awm[B*S];
__device__ float g_colmean[B*S];
__device__ float g_base[B*H];

// ---------------- PTX helpers ----------------
__device__ __forceinline__ uint32_t smem_u32(const void* p) {
    return (uint32_t)__cvta_generic_to_shared(p);
}
__device__ __forceinline__ void ldm_x4(uint32_t* r, uint32_t a) {
    asm volatile("ldmatrix.sync.aligned.m8n8.x4.shared.b16 {%0,%1,%2,%3}, [%4];"
        : "=r"(r[0]), "=r"(r[1]), "=r"(r[2]), "=r"(r[3]) : "r"(a));
}
__device__ __forceinline__ void mma_bf16(float* c, const uint32_t* a, const uint32_t* b) {
    asm volatile(
        "mma.sync.aligned.m16n8k16.row.col.f32.bf16.bf16.f32 "
        "{%0,%1,%2,%3},{%4,%5,%6,%7},{%8,%9},{%0,%1,%2,%3};"
        : "+f"(c[0]), "+f"(c[1]), "+f"(c[2]), "+f"(c[3])
        : "r"(a[0]), "r"(a[1]), "r"(a[2]), "r"(a[3]), "r"(b[0]), "r"(b[1]));
}
__device__ __forceinline__ void cpa16(uint32_t dst, const void* src) {
    asm volatile("cp.async.cg.shared.global [%0], [%1], 16;" :: "r"(dst), "l"(src));
}
__device__ __forceinline__ void cpa_commit() { asm volatile("cp.async.commit_group;"); }
__device__ __forceinline__ void cpa_wait1() { asm volatile("cp.async.wait_group 1;"); }
__device__ __forceinline__ void cpa_wait0() { asm volatile("cp.async.wait_group 0;"); }

__device__ __forceinline__ uint32_t h2_ex2(uint32_t x) {
    uint32_t r; asm("ex2.approx.f16x2 %0, %1;" : "=r"(r) : "r"(x)); return r;
}
__device__ __forceinline__ uint32_t h2_pack(float a, float b) {
    __half2 h = __floats2half2_rn(a, b);
    return *reinterpret_cast<uint32_t*>(&h);
}
__device__ __forceinline__ float2 h2_unpack(uint32_t u) {
    return __half22float2(*reinterpret_cast<__half2*>(&u));
}

// ---------------- fused prep ----------------
__global__ void prep_k(const float* __restrict__ x,
                       const float* __restrict__ Wq, const float* __restrict__ Wk,
                       const float* __restrict__ Wm1, const float* __restrict__ Wi1,
                       const float* __restrict__ Wi2, const float* __restrict__ We1) {
    int bid = blockIdx.x, t = threadIdx.x;
    if (bid < 4096) {
        int i = bid * 1024 + t * 4;
        float4 v = *(const float4*)(x + i);
        __nv_bfloat162* dst = (__nv_bfloat162*)(g_xh + i);
        dst[0] = __floats2bfloat162_rn(v.x, v.y);
        dst[1] = __floats2bfloat162_rn(v.z, v.w);
        return;
    }
    bid -= 4096;
    if (bid < 256) {
        int o = bid * 256 + t; int n = o >> 8, k = o & 255;
        g_WqkT[o] = __float2bfloat16(Wq[k * 256 + n]);
        return;
    }
    bid -= 256;
    if (bid < 256) {
        int o = bid * 256 + t; int n = o >> 8, k = o & 255;
        g_WqkT[65536 + o] = __float2bfloat16(Wk[k * 256 + n]);
        return;
    }
    bid -= 256;
    if (bid < 128) {
        int o = bid * 256 + t; int n = o >> 8, k = o & 255;
        g_WmiT[o] = __float2bfloat16(Wm1[k * 128 + n]);
        return;
    }
    bid -= 128;
    if (bid < 256) {
        int o = bid * 256 + t; int n = o >> 8, k = o & 255;
        g_WmiT[128 * 256 + o] = __float2bfloat16(Wi1[k * 256 + n]);
        return;
    }
    bid -= 256;
    if (bid < 256) {
        int o = bid * 256 + t; int n = o >> 8, k = o & 255;
        g_Wi2T[o] = __float2bfloat16(Wi2[k * 256 + n]);
        return;
    }
    bid -= 256;
    if (bid < 128) {
        int o = bid * 256 + t; int n = o >> 8, k = o & 255;
        g_We1T[o] = __float2bfloat16(We1[k * 128 + n]);
        return;
    }
    bid -= 128;
    if (bid < 64) {
        g_awsum[bid * 256 + t] = 0.f;
        return;
    }
    bid -= 64;
    g_base[bid * 256 + t] = 0.f;
}

// ---------------- shared GEMM pipeline body --------------------------------------
__device__ __forceinline__ void gemm_core(
    const __nv_bfloat16* __restrict__ Ah, const __nv_bfloat16* __restrict__ Bt,
    int row0, uint32_t sbase, int t, int wm, int wn, int lane,
    float acc[4][4][4])
{
    const int STB = 16384;
    auto load_stage = [&](int stage, int kt) {
        uint32_t sb = sbase + stage * STB;
#pragma unroll
        for (int i = 0; i < 2; i++) {
            int c = t + i * 256;
            int row = c >> 2, ch = c & 3;
            uint32_t d = (uint32_t)((row * 4 + (ch ^ ((row >> 1) & 3))) * 16);
            cpa16(sb + d, Ah + (size_t)(row0 + row) * 256 + kt * 32 + ch * 8);
            cpa16(sb + 8192 + d, Bt + (size_t)row * 256 + kt * 32 + ch * 8);
        }
    };
    load_stage(0, 0);
    cpa_commit();
    for (int kt = 0; kt < 8; kt++) {
        int st = kt & 1;
        if (kt < 7) { load_stage(st ^ 1, kt + 1); cpa_commit(); cpa_wait1(); }
        else cpa_wait0();
        __syncthreads();
        uint32_t sb = sbase + st * STB;
#pragma unroll
        for (int kk = 0; kk < 2; kk++) {
            uint32_t ah[4][4];
#pragma unroll
            for (int mt = 0; mt < 4; mt++) {
                int row = wm * 64 + mt * 16 + (lane & 15);
                int ch = kk * 2 + (lane >> 4);
                uint32_t off = (uint32_t)((row * 4 + (ch ^ ((row >> 1) & 3))) * 16);
                ldm_x4(ah[mt], sb + off);
            }
            uint32_t bh[4][2];
#pragma unroll
            for (int p = 0; p < 2; p++) {
                int row = wn * 32 + p * 16 + (lane & 7) + 8 * (lane >> 4);
                int ch = kk * 2 + ((lane >> 3) & 1);
                uint32_t off = (uint32_t)((row * 4 + (ch ^ ((row >> 1) & 3))) * 16);
                uint32_t r4[4];
                ldm_x4(r4, sb + 8192 + off);
                bh[2 * p][0] = r4[0]; bh[2 * p][1] = r4[1];
                bh[2 * p + 1][0] = r4[2]; bh[2 * p + 1][1] = r4[3];
            }
#pragma unroll
            for (int mt = 0; mt < 4; mt++)
#pragma unroll
                for (int nt = 0; nt < 4; nt++)
                    mma_bf16(acc[mt][nt], ah[mt], bh[nt]);
        }
        __syncthreads();
    }
}

// ---------------- merged QK | M1(strengths) | I1 GEMM ----------------------------
__global__ void __launch_bounds__(256) gemm_qkmi(
    const __nv_bfloat16* __restrict__ Ah,
    const float* __restrict__ bq, const float* __restrict__ bk,
    const float* __restrict__ bm1, const float* __restrict__ bi1,
    const float* __restrict__ Wm2, const float* __restrict__ bm2)
{
    extern __shared__ char smem[];
    int t = threadIdx.x, w = t >> 5, lane = t & 31;
    int bx = blockIdx.x;
    int row0 = blockIdx.y * 128;
    int wm = w & 1, wn = w >> 1;
    int g = lane >> 2, tq = lane & 3;

    const __nv_bfloat16* Bt = (bx < 4) ? (g_WqkT + (size_t)bx * 128 * 256)
                                       : (g_WmiT + (size_t)(bx - 4) * 128 * 256);

    float acc[4][4][4];
#pragma unroll
    for (int mt = 0; mt < 4; mt++)
#pragma unroll
        for (int nt = 0; nt < 4; nt++)
#pragma unroll
            for (int r = 0; r < 4; r++) acc[mt][nt][r] = 0.f;

    gemm_core(Ah, Bt, row0, smem_u32(smem), t, wm, wn, lane, acc);

    bool head = (bx == 4);
    float* st = (float*)smem;

#pragma unroll
    for (int mt = 0; mt < 4; mt++) {
        int rl = wm * 64 + mt * 16 + g;
#pragma unroll
        for (int nt = 0; nt < 4; nt++) {
            int cl = wn * 32 + nt * 8 + 2 * tq;
#pragma unroll
            for (int half = 0; half < 2; half++) {
                int rr = row0 + rl + 8 * half;
                float v0 = acc[mt][nt][2 * half];
                float v1 = acc[mt][nt][2 * half + 1];
                if (bx < 4) {
                    int gcol = bx * 128 + cl;
                    bool isk = (gcol >= 256);
                    v0 += isk ? bk[gcol - 256] : bq[gcol];
                    v1 += isk ? bk[gcol - 255] : bq[gcol + 1];
                    if (!isk) { v0 *= CEXP; v1 *= CEXP; }
                    *(__nv_bfloat162*)(g_qkh + (size_t)rr * 512 + gcol) =
                        __floats2bfloat162_rn(v0, v1);
                } else if (head) {
                    v0 = fmaxf(v0 + bm1[cl], 0.f);
                    v1 = fmaxf(v1 + bm1[cl + 1], 0.f);
                    st[(rl + 8 * half) * 129 + cl] = v0;
                    st[(rl + 8 * half) * 129 + cl + 1] = v1;
                } else {
                    int c2 = (bx - 5) * 128 + cl;
                    v0 = fmaxf(v0 + bi1[c2], 0.f);
                    v1 = fmaxf(v1 + bi1[c2 + 1], 0.f);
                    *(__nv_bfloat162*)(g_i1b + (size_t)rr * 256 + c2) =
                        __floats2bfloat162_rn(v0, v1);
                }
            }
        }
    }

    if (head) {
        __syncthreads();
        float wv[4];
#pragma unroll
        for (int i = 0; i < 4; i++) wv[i] = Wm2[lane + 32 * i];
        float hbv = bm2[0];
#pragma unroll
        for (int rr = w * 16; rr < w * 16 + 16; rr++) {
            float s = 0.f;
#pragma unroll
            for (int i = 0; i < 4; i++) s += wv[i] * st[rr * 129 + lane + 32 * i];
#pragma unroll
            for (int o = 16; o; o >>= 1) s += __shfl_xor_sync(0xFFFFFFFFu, s, o);
            if (lane == 0)
                g_str[row0 + rr] = 1.f / (1.f + __expf(-(s + hbv)));
        }
    }
}

// ---------------- I2+feats (MODE 2, + fused cm writer blocks) and E1+credit ------
template<int MODE>
__global__ void __launch_bounds__(256) gemm_mma(
    const __nv_bfloat16* __restrict__ Ah,
    const __nv_bfloat16* __restrict__ BTh,
    const float* __restrict__ bias0,
    const float* __restrict__ hw, const float* __restrict__ hb,
    const float* __restrict__ fin,
    void* out0, float* __restrict__ cmout)
{
    extern __shared__ char smem[];
    int t = threadIdx.x, w = t >> 5, lane = t & 31;

    if (MODE == 2 && blockIdx.x >= 2) {
        int blk = (blockIdx.x - 2) * 128 + blockIdx.y;
        int j4 = t;
        for (int r = 0; r < 64; r++) {
            int bi = blk * 64 + r;
            int b = bi >> 10, i = bi & 1023;
            float stv = g_str[bi];
            float4 a = ((const float4*)(g_awm + b * S))[j4];
            int j = j4 * 4;
            float4 v;
            v.x = (i >= j)     ? a.x * stv : 0.f;
            v.y = (i >= j + 1) ? a.y * stv : 0.f;
            v.z = (i >= j + 2) ? a.z * stv : 0.f;
            v.w = (i >= j + 3) ? a.w * stv : 0.f;
            ((float4*)(cmout + (size_t)bi * S))[j4] = v;
        }
        return;
    }

    int row0 = blockIdx.y * 128, col0 = blockIdx.x * 128;
    int wm = w & 1, wn = w >> 1;
    int g = lane >> 2, tq = lane & 3;

    float acc[4][4][4];
#pragma unroll
    for (int mt = 0; mt < 4; mt++)
#pragma unroll
        for (int nt = 0; nt < 4; nt++)
#pragma unroll
            for (int r = 0; r < 4; r++) acc[mt][nt][r] = 0.f;

    gemm_core(Ah, BTh + (size_t)col0 * 256, row0, smem_u32(smem), t, wm, wn, lane, acc);

    float* st = (float*)smem;

#pragma unroll
    for (int mt = 0; mt < 4; mt++) {
        int rl = wm * 64 + mt * 16 + g;
#pragma unroll
        for (int nt = 0; nt < 4; nt++) {
            int cl = wn * 32 + nt * 8 + 2 * tq;
            int colb = col0 + cl;
#pragma unroll
            for (int half = 0; half < 2; half++) {
                int rr = row0 + rl + 8 * half;
                float v0 = acc[mt][nt][2 * half];
                float v1 = acc[mt][nt][2 * half + 1];
                if (MODE == 2) {
                    v0 = 0.1f * tanhf(v0 + bias0[colb]);
                    v1 = 0.1f * tanhf(v1 + bias0[colb + 1]);
                    float cmv = g_colmean[rr] * (1.f / S);
                    int bb = row0 >> 10;
                    float f0 = g_base[bb * H + colb] + v0 * cmv;
                    float f1 = g_base[bb * H + colb + 1] + v1 * cmv;
                    *(__nv_bfloat162*)((__nv_bfloat16*)out0 + (size_t)rr * 256 + colb) =
                        __floats2bfloat162_rn(f0, f1);
                } else {
                    v0 = fmaxf(v0 + bias0[colb], 0.f);
                    v1 = fmaxf(v1 + bias0[colb + 1], 0.f);
                    st[(rl + 8 * half) * 129 + cl] = v0;
                    st[(rl + 8 * half) * 129 + cl + 1] = v1;
                }
            }
        }
    }

    if (MODE == 3) {
        __syncthreads();
        float wv[4];
#pragma unroll
        for (int i = 0; i < 4; i++) wv[i] = hw[lane + 32 * i];
        float hbv = hb[0];
        int bb = row0 >> 10;
#pragma unroll
        for (int rr = w * 16; rr < w * 16 + 16; rr++) {
            float s = 0.f;
#pragma unroll
            for (int i = 0; i < 4; i++) s += wv[i] * st[rr * 129 + lane + 32 * i];
#pragma unroll
            for (int o = 16; o; o >>= 1) s += __shfl_xor_sync(0xFFFFFFFFu, s, o);
            if (lane == 0)
                ((float*)out0)[row0 + rr] = fin[bb] - (s + hbv);
        }
    }
}

// ---------------- attention: 512 thr, 2 q-tiles per block (K reuse x2) -----------
// 16 warps: qh = w>>3 picks 32-row q-subtile, wn = w&7 picks 16 cols.
#define ES_PITCH 1048
#define ATTN_SMEM (32768 + 8192 + 64*ES_PITCH*2 + 2048 + 256)
__global__ void __launch_bounds__(512) attn_mma() {
    extern __shared__ char smem[];
    char* Kst = smem;
    char* Qsm = smem + 32768;
    __half* Es = (__half*)(Qsm + 8192);
    float* rpart = (float*)(smem + 32768 + 8192 + 64 * ES_PITCH * 2); // [16][32]
    float* rden = rpart + 512;                                        // [64]

    int t = threadIdx.x, w = t >> 5, lane = t & 31;
    int qt = blockIdx.x & 15;           // 16 q-tiles of 64 rows
    int bh = blockIdx.x >> 4;
    int b = bh >> 2, h = bh & 3;
    int q0 = qt * 64;
    int qh = w >> 3;                    // 0..1 : q-subtile
    int wn = w & 7;                     // 0..7 : 16 cols each
    int g = lane >> 2, tq = lane & 3;

    uint32_t kbase = smem_u32(Kst);
    uint32_t qbase = smem_u32(Qsm);

    // load Q tile (64x64), swizzled; 512 chunks, one per thread
    {
        int row = t >> 3, ch = t & 7;
        const __nv_bfloat16* sh = g_qkh + (size_t)(b * S + q0 + row) * 512 + h * DH + ch * 8;
        uint32_t d = (uint32_t)((row * 8 + (ch ^ (row & 7))) * 16);
        *(uint4*)(Qsm + d) = *(const uint4*)sh;
    }

    auto load_K = [&](int stage, int kt) {
        uint32_t sbk = kbase + stage * 16384;
#pragma unroll
        for (int i = 0; i < 2; i++) {
            int c = t + i * 512;
            int j = c >> 3, ch = c & 7;
            uint32_t d = (uint32_t)((j * 8 + (ch ^ (j & 7))) * 16);
            size_t src = (size_t)(b * S + kt * 128 + j) * 512 + 256 + h * DH + ch * 8;
            cpa16(sbk + d, g_qkh + src);
        }
    };

    load_K(0, 0);
    cpa_commit();
    __syncthreads();                 // Q STS visible

    // hoist Q fragments for this warp's 32 rows: 2 mt x 4 d16
    uint32_t aq[2][4][4];
#pragma unroll
    for (int mt = 0; mt < 2; mt++)
#pragma unroll
        for (int d16 = 0; d16 < 4; d16++) {
            int row = qh * 32 + mt * 16 + (lane & 15);
            int ch = d16 * 2 + (lane >> 4);
            uint32_t off = (uint32_t)((row * 8 + (ch ^ (row & 7))) * 16);
            ldm_x4(aq[mt][d16], qbase + off);
        }

    float rsum[4] = {0.f, 0.f, 0.f, 0.f};   // local rows i*8+g (i = mt*2+half)

    for (int kt = 0; kt < 8; kt++) {
        int stg = kt & 1;
        if (kt < 7) { load_K(stg ^ 1, kt + 1); cpa_commit(); cpa_wait1(); }
        else cpa_wait0();
        __syncthreads();
        uint32_t sbk = kbase + stg * 16384;

        float acc[2][2][4];
#pragma unroll
        for (int mt = 0; mt < 2; mt++)
#pragma unroll
            for (int nt = 0; nt < 2; nt++)
#pragma unroll
                for (int r = 0; r < 4; r++) acc[mt][nt][r] = 0.f;

#pragma unroll
        for (int d16 = 0; d16 < 4; d16++) {
            int j = wn * 16 + (lane & 7) + 8 * (lane >> 4);
            int ch = d16 * 2 + ((lane >> 3) & 1);
            uint32_t off = (uint32_t)((j * 8 + (ch ^ (j & 7))) * 16);
            uint32_t r4[4];
            ldm_x4(r4, sbk + off);
            uint32_t bh2[2][2];
            bh2[0][0] = r4[0]; bh2[0][1] = r4[1];
            bh2[1][0] = r4[2]; bh2[1][1] = r4[3];
#pragma unroll
            for (int mt = 0; mt < 2; mt++)
#pragma unroll
                for (int nt = 0; nt < 2; nt++)
                    mma_bf16(acc[mt][nt], aq[mt][d16], bh2[nt]);
        }
#pragma unroll
        for (int mt = 0; mt < 2; mt++)
#pragma unroll
            for (int nt = 0; nt < 2; nt++) {
                int colb = kt * 128 + wn * 16 + nt * 8 + 2 * tq;
                uint32_t e0 = h2_ex2(h2_pack(acc[mt][nt][0], acc[mt][nt][1]));
                uint32_t e1 = h2_ex2(h2_pack(acc[mt][nt][2], acc[mt][nt][3]));
                float2 f0 = h2_unpack(e0);
                float2 f1 = h2_unpack(e1);
                rsum[mt * 2]     += f0.x + f0.y;
                rsum[mt * 2 + 1] += f1.x + f1.y;
                int r0 = qh * 32 + mt * 16 + g;
                *(uint32_t*)&Es[r0 * ES_PITCH + colb] = e0;
                *(uint32_t*)&Es[(r0 + 8) * ES_PITCH + colb] = e1;
            }
        __syncthreads();
    }

    // row sums: reduce over tq lanes, stash per-warp partials
#pragma unroll
    for (int i = 0; i < 4; i++) {
        rsum[i] += __shfl_xor_sync(0xFFFFFFFFu, rsum[i], 1);
        rsum[i] += __shfl_xor_sync(0xFFFFFFFFu, rsum[i], 2);
    }
    if (tq == 0) {
#pragma unroll
        for (int i = 0; i < 4; i++)
            rpart[w * 32 + i * 8 + g] = rsum[i];
    }
    __syncthreads();
    if (t < 64) {                       // row r = t (0..63)
        int qr = t >> 5, r32 = t & 31;
        float s = 0.f;
#pragma unroll
        for (int ww = 0; ww < 8; ww++) s += rpart[(qr * 8 + ww) * 32 + r32];
        rden[t] = 1.f / s;
    }
    __syncthreads();

    // column sums over 64 rows (half2 reads) -> global accumulation
    {
        int j2 = t;                     // 0..511
        float sx = 0.f, sy = 0.f;
#pragma unroll
        for (int r = 0; r < 64; r++) {
            float2 e = __half22float2(((__half2*)(Es + r * ES_PITCH))[j2]);
            float rd = rden[r];
            sx += e.x * rd;
            sy += e.y * rd;
        }
        atomicAdd(&g_awsum[b * S + 2 * j2], sx);
        atomicAdd(&g_awsum[b * S + 2 * j2 + 1], sy);
    }
}

// ---------------- colmean (shfl suffix scan) + parallel base ---------------------
__global__ void __launch_bounds__(1024) colmean_base_k() {
    __shared__ float wtot[32], woff[32], cmb[1024], bacc[4][256];
    int b = blockIdx.x, sc = blockIdx.y, j = threadIdx.x;
    int lane = j & 31, wid = j >> 5;
    float v = g_str[b * S + j];
    // inclusive suffix scan within warp (sum over lanes >= lane)
#pragma unroll
    for (int off = 1; off < 32; off <<= 1) {
        float o = __shfl_down_sync(0xFFFFFFFFu, v, off);
        if (lane + off < 32) v += o;
    }
    if (lane == 0) wtot[wid] = v;     // warp total
    __syncthreads();
    if (j < 32) {
        float wv = wtot[j];
        float sv = wv;
#pragma unroll
        for (int off = 1; off < 32; off <<= 1) {
            float o = __shfl_down_sync(0xFFFFFFFFu, sv, off);
            if (lane + off < 32) sv += o;
        }
        woff[j] = sv - wv;            // exclusive suffix over warps
    }
    __syncthreads();
    float suf = v + woff[wid];
    float awm = g_awsum[b * S + j] * (1.f / (NH * S));
    float cmv = awm * suf * (1.f / S);
    if (sc == 0) {
        g_awm[b * S + j] = awm;
        g_colmean[b * S + j] = cmv;
    }
    cmb[j] = cmv;
    __syncthreads();
    int h = j & 255, sg = j >> 8;
    const __nv_bfloat16* xb = g_xh + (size_t)b * S * H;
    int sbeg = sc * 128 + sg * 32;
    float a = 0.f;
    for (int s = sbeg; s < sbeg + 32; s++)
        a += __bfloat162float(xb[(size_t)s * H + h]) * cmb[s];
    bacc[sg][h] = a;
    __syncthreads();
    if (j < 256)
        atomicAdd(&g_base[b * H + j],
                  (bacc[0][j] + bacc[1][j] + bacc[2][j] + bacc[3][j]) * (1.f / S));
}

// ---------------- launch ----------------
extern "C" void kernel_launch(void* const* d_in, const int* in_sizes, int n_in,
                              void* d_out, int out_size) {
    const float* x    = (const float*)d_in[0];
    const float* fin  = (const float*)d_in[1];
    const float* Wq   = (const float*)d_in[3];
    const float* bq   = (const float*)d_in[4];
    const float* Wk   = (const float*)d_in[5];
    const float* bk   = (const float*)d_in[6];
    const float* Wm1  = (const float*)d_in[7];
    const float* bm1  = (const float*)d_in[8];
    const float* Wm2  = (const float*)d_in[9];
    const float* bm2  = (const float*)d_in[10];
    const float* Wi1  = (const float*)d_in[11];
    const float* bi1  = (const float*)d_in[12];
    const float* Wi2  = (const float*)d_in[13];
    const float* bi2  = (const float*)d_in[14];
    const float* We1  = (const float*)d_in[15];
    const float* be1  = (const float*)d_in[16];
    const float* We2  = (const float*)d_in[17];
    const float* be2  = (const float*)d_in[18];
    float* out = (float*)d_out;

    __nv_bfloat16 *pxh, *pWi2T, *pWe1T, *pi1b, *pfb;
    cudaGetSymbolAddress((void**)&pxh, g_xh);
    cudaGetSymbolAddress((void**)&pWi2T, g_Wi2T);
    cudaGetSymbolAddress((void**)&pWe1T, g_We1T);
    cudaGetSymbolAddress((void**)&pi1b, g_i1b);
    cudaGetSymbolAddress((void**)&pfb, g_fb);

    const int SM_1P = 32768, SM_HEAD = 66048;
    cudaFuncSetAttribute(gemm_qkmi, cudaFuncAttributeMaxDynamicSharedMemorySize, SM_HEAD);
    cudaFuncSetAttribute(gemm_mma<2>, cudaFuncAttributeMaxDynamicSharedMemorySize, SM_1P);
    cudaFuncSetAttribute(gemm_mma<3>, cudaFuncAttributeMaxDynamicSharedMemorySize, SM_HEAD);
    cudaFuncSetAttribute(attn_mma, cudaFuncAttributeMaxDynamicSharedMemorySize, ATTN_SMEM);

    // 1. prep
    prep_k<<<5456, 256>>>(x, Wq, Wk, Wm1, Wi1, Wi2, We1);

    // 2. merged QK | strengths | I1
    gemm_qkmi<<<dim3(7,128), 256, SM_HEAD>>>(pxh, bq, bk, bm1, bi1, Wm2, bm2);

    // 3. attention column sums (2 q-tiles per block)
    attn_mma<<<B*NH*16, 512, ATTN_SMEM>>>();

    // 4. colmean (shfl scan) + base
    colmean_base_k<<<dim3(B,8), 1024>>>();

    // 5. I2 + fused feats + cm writers -> out[B*S:]
    gemm_mma<2><<<dim3(4,128), 256, SM_1P>>>(pi1b, pWi2T, bi2,
                                             nullptr, nullptr, nullptr, pfb, out + B*S);
    // 6. E1 + fused credit head -> out[0 : B*S]
    gemm_mma<3><<<dim3(1,128), 256, SM_HEAD>>>(pfb, pWe1T, be1,
                                               We2, be2, fin, out, nullptr);
}

// round 13
// speedup vs baseline: 1.0498x; 1.0498x over previous
#include <cuda_runtime.h>
#include <cuda_bf16.h>
#include <cuda_fp16.h>
#include <math.h>
#include <stdint.h>

#define B 16
#define S 1024
#define H 256
#define NH 4
#define DH 64
#define H2 128
#define MROWS (B*S)   // 16384
#define CEXP (0.125f * 1.44269504f)

// ---------------- scratch (static device globals) ----------------
__device__ __align__(16) __nv_bfloat16 g_xh[MROWS*H];
__device__ __align__(16) __nv_bfloat16 g_WqkT[512*H];
__device__ __align__(16) __nv_bfloat16 g_WmiT[384*H];
__device__ __align__(16) __nv_bfloat16 g_Wi2T[H*H];
__device__ __align__(16) __nv_bfloat16 g_We1T[H2*H];
__device__ __align__(16) __nv_bfloat16 g_qkh[MROWS*512];
__device__ __align__(16) __nv_bfloat16 g_i1b[MROWS*H];
__device__ float g_str[B*S];
__device__ float g_awsum[B*S];
__device__ float g_awm[B*S];
__device__ float g_colmean[B*S];
__device__ float g_base[B*H];

// ---------------- PTX helpers ----------------
__device__ __forceinline__ uint32_t smem_u32(const void* p) {
    return (uint32_t)__cvta_generic_to_shared(p);
}
__device__ __forceinline__ void ldm_x4(uint32_t* r, uint32_t a) {
    asm volatile("ldmatrix.sync.aligned.m8n8.x4.shared.b16 {%0,%1,%2,%3}, [%4];"
        : "=r"(r[0]), "=r"(r[1]), "=r"(r[2]), "=r"(r[3]) : "r"(a));
}
__device__ __forceinline__ void mma_bf16(float* c, const uint32_t* a, const uint32_t* b) {
    asm volatile(
        "mma.sync.aligned.m16n8k16.row.col.f32.bf16.bf16.f32 "
        "{%0,%1,%2,%3},{%4,%5,%6,%7},{%8,%9},{%0,%1,%2,%3};"
        : "+f"(c[0]), "+f"(c[1]), "+f"(c[2]), "+f"(c[3])
        : "r"(a[0]), "r"(a[1]), "r"(a[2]), "r"(a[3]), "r"(b[0]), "r"(b[1]));
}
__device__ __forceinline__ void cpa16(uint32_t dst, const void* src) {
    asm volatile("cp.async.cg.shared.global [%0], [%1], 16;" :: "r"(dst), "l"(src));
}
__device__ __forceinline__ void cpa_commit() { asm volatile("cp.async.commit_group;"); }
__device__ __forceinline__ void cpa_wait1() { asm volatile("cp.async.wait_group 1;"); }
__device__ __forceinline__ void cpa_wait0() { asm volatile("cp.async.wait_group 0;"); }

__device__ __forceinline__ uint32_t h2_ex2(uint32_t x) {
    uint32_t r; asm("ex2.approx.f16x2 %0, %1;" : "=r"(r) : "r"(x)); return r;
}
__device__ __forceinline__ uint32_t h2_pack(float a, float b) {
    __half2 h = __floats2half2_rn(a, b);
    return *reinterpret_cast<uint32_t*>(&h);
}
__device__ __forceinline__ float2 h2_unpack(uint32_t u) {
    return __half22float2(*reinterpret_cast<__half2*>(&u));
}

// ---------------- fused prep ----------------
__global__ void prep_k(const float* __restrict__ x,
                       const float* __restrict__ Wq, const float* __restrict__ Wk,
                       const float* __restrict__ Wm1, const float* __restrict__ Wi1,
                       const float* __restrict__ Wi2, const float* __restrict__ We1) {
    int bid = blockIdx.x, t = threadIdx.x;
    if (bid < 4096) {
        int i = bid * 1024 + t * 4;
        float4 v = *(const float4*)(x + i);
        __nv_bfloat162* dst = (__nv_bfloat162*)(g_xh + i);
        dst[0] = __floats2bfloat162_rn(v.x, v.y);
        dst[1] = __floats2bfloat162_rn(v.z, v.w);
        return;
    }
    bid -= 4096;
    if (bid < 256) {
        int o = bid * 256 + t; int n = o >> 8, k = o & 255;
        g_WqkT[o] = __float2bfloat16(Wq[k * 256 + n]);
        return;
    }
    bid -= 256;
    if (bid < 256) {
        int o = bid * 256 + t; int n = o >> 8, k = o & 255;
        g_WqkT[65536 + o] = __float2bfloat16(Wk[k * 256 + n]);
        return;
    }
    bid -= 256;
    if (bid < 128) {
        int o = bid * 256 + t; int n = o >> 8, k = o & 255;
        g_WmiT[o] = __float2bfloat16(Wm1[k * 128 + n]);
        return;
    }
    bid -= 128;
    if (bid < 256) {
        int o = bid * 256 + t; int n = o >> 8, k = o & 255;
        g_WmiT[128 * 256 + o] = __float2bfloat16(Wi1[k * 256 + n]);
        return;
    }
    bid -= 256;
    if (bid < 256) {
        int o = bid * 256 + t; int n = o >> 8, k = o & 255;
        g_Wi2T[o] = __float2bfloat16(Wi2[k * 256 + n]);
        return;
    }
    bid -= 256;
    if (bid < 128) {
        int o = bid * 256 + t; int n = o >> 8, k = o & 255;
        g_We1T[o] = __float2bfloat16(We1[k * 128 + n]);
        return;
    }
    bid -= 128;
    if (bid < 64) {
        g_awsum[bid * 256 + t] = 0.f;
        return;
    }
    bid -= 64;
    g_base[bid * 256 + t] = 0.f;
}

// ---------------- shared GEMM pipeline body (256-thr, 128x128 tile) --------------
__device__ __forceinline__ void gemm_core(
    const __nv_bfloat16* __restrict__ Ah, const __nv_bfloat16* __restrict__ Bt,
    int row0, uint32_t sbase, int t, int wm, int wn, int lane,
    float acc[4][4][4])
{
    const int STB = 16384;
    auto load_stage = [&](int stage, int kt) {
        uint32_t sb = sbase + stage * STB;
#pragma unroll
        for (int i = 0; i < 2; i++) {
            int c = t + i * 256;
            int row = c >> 2, ch = c & 3;
            uint32_t d = (uint32_t)((row * 4 + (ch ^ ((row >> 1) & 3))) * 16);
            cpa16(sb + d, Ah + (size_t)(row0 + row) * 256 + kt * 32 + ch * 8);
            cpa16(sb + 8192 + d, Bt + (size_t)row * 256 + kt * 32 + ch * 8);
        }
    };
    load_stage(0, 0);
    cpa_commit();
    for (int kt = 0; kt < 8; kt++) {
        int st = kt & 1;
        if (kt < 7) { load_stage(st ^ 1, kt + 1); cpa_commit(); cpa_wait1(); }
        else cpa_wait0();
        __syncthreads();
        uint32_t sb = sbase + st * STB;
#pragma unroll
        for (int kk = 0; kk < 2; kk++) {
            uint32_t ah[4][4];
#pragma unroll
            for (int mt = 0; mt < 4; mt++) {
                int row = wm * 64 + mt * 16 + (lane & 15);
                int ch = kk * 2 + (lane >> 4);
                uint32_t off = (uint32_t)((row * 4 + (ch ^ ((row >> 1) & 3))) * 16);
                ldm_x4(ah[mt], sb + off);
            }
            uint32_t bh[4][2];
#pragma unroll
            for (int p = 0; p < 2; p++) {
                int row = wn * 32 + p * 16 + (lane & 7) + 8 * (lane >> 4);
                int ch = kk * 2 + ((lane >> 3) & 1);
                uint32_t off = (uint32_t)((row * 4 + (ch ^ ((row >> 1) & 3))) * 16);
                uint32_t r4[4];
                ldm_x4(r4, sb + 8192 + off);
                bh[2 * p][0] = r4[0]; bh[2 * p][1] = r4[1];
                bh[2 * p + 1][0] = r4[2]; bh[2 * p + 1][1] = r4[3];
            }
#pragma unroll
            for (int mt = 0; mt < 4; mt++)
#pragma unroll
                for (int nt = 0; nt < 4; nt++)
                    mma_bf16(acc[mt][nt], ah[mt], bh[nt]);
        }
        __syncthreads();
    }
}

// ---------------- merged QK | M1(strengths) | I1 GEMM ----------------------------
__global__ void __launch_bounds__(256) gemm_qkmi(
    const __nv_bfloat16* __restrict__ Ah,
    const float* __restrict__ bq, const float* __restrict__ bk,
    const float* __restrict__ bm1, const float* __restrict__ bi1,
    const float* __restrict__ Wm2, const float* __restrict__ bm2)
{
    extern __shared__ char smem[];
    int t = threadIdx.x, w = t >> 5, lane = t & 31;
    int bx = blockIdx.x;
    int row0 = blockIdx.y * 128;
    int wm = w & 1, wn = w >> 1;
    int g = lane >> 2, tq = lane & 3;

    const __nv_bfloat16* Bt = (bx < 4) ? (g_WqkT + (size_t)bx * 128 * 256)
                                       : (g_WmiT + (size_t)(bx - 4) * 128 * 256);

    float acc[4][4][4];
#pragma unroll
    for (int mt = 0; mt < 4; mt++)
#pragma unroll
        for (int nt = 0; nt < 4; nt++)
#pragma unroll
            for (int r = 0; r < 4; r++) acc[mt][nt][r] = 0.f;

    gemm_core(Ah, Bt, row0, smem_u32(smem), t, wm, wn, lane, acc);

    bool head = (bx == 4);
    float* st = (float*)smem;

#pragma unroll
    for (int mt = 0; mt < 4; mt++) {
        int rl = wm * 64 + mt * 16 + g;
#pragma unroll
        for (int nt = 0; nt < 4; nt++) {
            int cl = wn * 32 + nt * 8 + 2 * tq;
#pragma unroll
            for (int half = 0; half < 2; half++) {
                int rr = row0 + rl + 8 * half;
                float v0 = acc[mt][nt][2 * half];
                float v1 = acc[mt][nt][2 * half + 1];
                if (bx < 4) {
                    int gcol = bx * 128 + cl;
                    bool isk = (gcol >= 256);
                    v0 += isk ? bk[gcol - 256] : bq[gcol];
                    v1 += isk ? bk[gcol - 255] : bq[gcol + 1];
                    if (!isk) { v0 *= CEXP; v1 *= CEXP; }
                    *(__nv_bfloat162*)(g_qkh + (size_t)rr * 512 + gcol) =
                        __floats2bfloat162_rn(v0, v1);
                } else if (head) {
                    v0 = fmaxf(v0 + bm1[cl], 0.f);
                    v1 = fmaxf(v1 + bm1[cl + 1], 0.f);
                    st[(rl + 8 * half) * 129 + cl] = v0;
                    st[(rl + 8 * half) * 129 + cl + 1] = v1;
                } else {
                    int c2 = (bx - 5) * 128 + cl;
                    v0 = fmaxf(v0 + bi1[c2], 0.f);
                    v1 = fmaxf(v1 + bi1[c2 + 1], 0.f);
                    *(__nv_bfloat162*)(g_i1b + (size_t)rr * 256 + c2) =
                        __floats2bfloat162_rn(v0, v1);
                }
            }
        }
    }

    if (head) {
        __syncthreads();
        float wv[4];
#pragma unroll
        for (int i = 0; i < 4; i++) wv[i] = Wm2[lane + 32 * i];
        float hbv = bm2[0];
#pragma unroll
        for (int rr = w * 16; rr < w * 16 + 16; rr++) {
            float s = 0.f;
#pragma unroll
            for (int i = 0; i < 4; i++) s += wv[i] * st[rr * 129 + lane + 32 * i];
#pragma unroll
            for (int o = 16; o; o >>= 1) s += __shfl_xor_sync(0xFFFFFFFFu, s, o);
            if (lane == 0)
                g_str[row0 + rr] = 1.f / (1.f + __expf(-(s + hbv)));
        }
    }
}

// ---------------- fused I2->feats(smem)->E1->credit, plus cm writers -------------
// 1-D grid: bx<128 -> GEMM chain for rows bx*128..+128; bx>=128 -> cm writer.
// smem layout: PH1 stages [0,49152) | feats 8x8KB [49152,114688) |
//              B2 stages [114688,131072) | st [131072,131072+66048)
#define FE_SMEM (49152 + 65536 + 16384 + 66048)
__device__ __forceinline__ uint32_t feats_off(int r, int c) {  // c even
    return (uint32_t)(49152 + (c >> 5) * 8192 +
                      (r * 4 + (((c >> 3) & 3) ^ ((r >> 1) & 3))) * 16 + (c & 7) * 2);
}
__global__ void __launch_bounds__(512) gemm_fe(
    const __nv_bfloat16* __restrict__ Ah,        // i1b
    const __nv_bfloat16* __restrict__ Bt1,       // Wi2T [256,256]
    const __nv_bfloat16* __restrict__ Bt2,       // We1T [128,256]
    const float* __restrict__ bi2, const float* __restrict__ be1,
    const float* __restrict__ We2, const float* __restrict__ be2,
    const float* __restrict__ fin,
    float* __restrict__ credit, float* __restrict__ cmout)
{
    extern __shared__ char smem[];
    int t = threadIdx.x, w = t >> 5, lane = t & 31;

    if (blockIdx.x >= 128) {       // cm writer: 256 blocks x 64 rows
        int blk = blockIdx.x - 128;
        int j4 = t & 255;
        int rh = t >> 8;           // 0..1
        for (int r = rh * 32; r < rh * 32 + 32; r++) {
            int bi = blk * 64 + r;
            int b = bi >> 10, i = bi & 1023;
            float stv = g_str[bi];
            float4 a = ((const float4*)(g_awm + b * S))[j4];
            int j = j4 * 4;
            float4 v;
            v.x = (i >= j)     ? a.x * stv : 0.f;
            v.y = (i >= j + 1) ? a.y * stv : 0.f;
            v.z = (i >= j + 2) ? a.z * stv : 0.f;
            v.w = (i >= j + 3) ? a.w * stv : 0.f;
            ((float4*)(cmout + (size_t)bi * S))[j4] = v;
        }
        return;
    }

    int row0 = blockIdx.x * 128;
    int bb = row0 >> 10;
    int g = lane >> 2, tq = lane & 3;
    uint32_t sbase = smem_u32(smem);

    // ---- phase 1: d2 = i1[row0:+128,:] @ Wi2T  (tile 128x256, K=256) ----
    {
        int wm = w & 1, wn = w >> 1;      // 2 x 8 warps: 64 rows x 32 cols
        const int STB = 24576;
        auto load_stage = [&](int stage, int kt) {
            uint32_t sb = sbase + stage * STB;
            {   // A: 512 chunks
                int c = t;
                int row = c >> 2, ch = c & 3;
                uint32_t d = (uint32_t)((row * 4 + (ch ^ ((row >> 1) & 3))) * 16);
                cpa16(sb + d, Ah + (size_t)(row0 + row) * 256 + kt * 32 + ch * 8);
            }
#pragma unroll
            for (int i = 0; i < 2; i++) {  // B: 1024 chunks
                int c = t + i * 512;
                int row = c >> 2, ch = c & 3;
                uint32_t d = (uint32_t)((row * 4 + (ch ^ ((row >> 1) & 3))) * 16);
                cpa16(sb + 8192 + d, Bt1 + (size_t)row * 256 + kt * 32 + ch * 8);
            }
        };
        float acc[4][4][4];
#pragma unroll
        for (int mt = 0; mt < 4; mt++)
#pragma unroll
            for (int nt = 0; nt < 4; nt++)
#pragma unroll
                for (int r = 0; r < 4; r++) acc[mt][nt][r] = 0.f;

        load_stage(0, 0);
        cpa_commit();
        for (int kt = 0; kt < 8; kt++) {
            int st = kt & 1;
            if (kt < 7) { load_stage(st ^ 1, kt + 1); cpa_commit(); cpa_wait1(); }
            else cpa_wait0();
            __syncthreads();
            uint32_t sb = sbase + st * STB;
#pragma unroll
            for (int kk = 0; kk < 2; kk++) {
                uint32_t ah[4][4];
#pragma unroll
                for (int mt = 0; mt < 4; mt++) {
                    int row = wm * 64 + mt * 16 + (lane & 15);
                    int ch = kk * 2 + (lane >> 4);
                    uint32_t off = (uint32_t)((row * 4 + (ch ^ ((row >> 1) & 3))) * 16);
                    ldm_x4(ah[mt], sb + off);
                }
                uint32_t bh[4][2];
#pragma unroll
                for (int p = 0; p < 2; p++) {
                    int row = wn * 32 + p * 16 + (lane & 7) + 8 * (lane >> 4);
                    int ch = kk * 2 + ((lane >> 3) & 1);
                    uint32_t off = (uint32_t)((row * 4 + (ch ^ ((row >> 1) & 3))) * 16);
                    uint32_t r4[4];
                    ldm_x4(r4, sb + 8192 + off);
                    bh[2 * p][0] = r4[0]; bh[2 * p][1] = r4[1];
                    bh[2 * p + 1][0] = r4[2]; bh[2 * p + 1][1] = r4[3];
                }
#pragma unroll
                for (int mt = 0; mt < 4; mt++)
#pragma unroll
                    for (int nt = 0; nt < 4; nt++)
                        mma_bf16(acc[mt][nt], ah[mt], bh[nt]);
            }
            __syncthreads();
        }

        // prefetch phase-2 B stage 0 (overlaps epilogue)
        {
            int c = t;  // 512 chunks: 128 rows x 4 ch
            int row = c >> 2, ch = c & 3;
            uint32_t d = (uint32_t)((row * 4 + (ch ^ ((row >> 1) & 3))) * 16);
            cpa16(sbase + 114688 + d, Bt2 + (size_t)row * 256 + ch * 8);
        }
        cpa_commit();

        // epilogue 1: feats -> smem (bf16, chunked swizzled layout)
#pragma unroll
        for (int mt = 0; mt < 4; mt++) {
            int rl = wm * 64 + mt * 16 + g;
#pragma unroll
            for (int nt = 0; nt < 4; nt++) {
                int cl = wn * 32 + nt * 8 + 2 * tq;
#pragma unroll
                for (int half = 0; half < 2; half++) {
                    int r = rl + 8 * half;
                    float v0 = 0.1f * tanhf(acc[mt][nt][2 * half] + bi2[cl]);
                    float v1 = 0.1f * tanhf(acc[mt][nt][2 * half + 1] + bi2[cl + 1]);
                    float cmv = g_colmean[row0 + r] * (1.f / S);
                    float f0 = g_base[bb * H + cl] + v0 * cmv;
                    float f1 = g_base[bb * H + cl + 1] + v1 * cmv;
                    *(__nv_bfloat162*)(smem + feats_off(r, cl)) =
                        __floats2bfloat162_rn(f0, f1);
                }
            }
        }
    }

    // ---- phase 2: o1 = relu(feats @ We1T + be1); credit head ----
    float* st = (float*)(smem + 131072);
    {
        int wm2 = w & 1, wn2 = w >> 1;   // 2 x 8 warps: 64 rows x 16 cols
        auto load_B2 = [&](int stage, int kt) {
            uint32_t sb = sbase + 114688 + stage * 8192;
            int c = t;
            int row = c >> 2, ch = c & 3;
            uint32_t d = (uint32_t)((row * 4 + (ch ^ ((row >> 1) & 3))) * 16);
            cpa16(sb + d, Bt2 + (size_t)row * 256 + kt * 32 + ch * 8);
        };
        float acc2[4][2][4];
#pragma unroll
        for (int mt = 0; mt < 4; mt++)
#pragma unroll
            for (int nt = 0; nt < 2; nt++)
#pragma unroll
                for (int r = 0; r < 4; r++) acc2[mt][nt][r] = 0.f;

        for (int kt = 0; kt < 8; kt++) {
            int st2 = kt & 1;
            if (kt < 7) { load_B2(st2 ^ 1, kt + 1); cpa_commit(); cpa_wait1(); }
            else cpa_wait0();
            __syncthreads();
            uint32_t ab = sbase + 49152 + kt * 8192;
            uint32_t bbse = sbase + 114688 + st2 * 8192;
#pragma unroll
            for (int kk = 0; kk < 2; kk++) {
                uint32_t ah[4][4];
#pragma unroll
                for (int mt = 0; mt < 4; mt++) {
                    int row = wm2 * 64 + mt * 16 + (lane & 15);
                    int ch = kk * 2 + (lane >> 4);
                    uint32_t off = (uint32_t)((row * 4 + (ch ^ ((row >> 1) & 3))) * 16);
                    ldm_x4(ah[mt], ab + off);
                }
                uint32_t bh2[2][2];
                {
                    int row = wn2 * 16 + (lane & 7) + 8 * (lane >> 4);
                    int ch = kk * 2 + ((lane >> 3) & 1);
                    uint32_t off = (uint32_t)((row * 4 + (ch ^ ((row >> 1) & 3))) * 16);
                    uint32_t r4[4];
                    ldm_x4(r4, bbse + off);
                    bh2[0][0] = r4[0]; bh2[0][1] = r4[1];
                    bh2[1][0] = r4[2]; bh2[1][1] = r4[3];
                }
#pragma unroll
                for (int mt = 0; mt < 4; mt++)
#pragma unroll
                    for (int nt = 0; nt < 2; nt++)
                        mma_bf16(acc2[mt][nt], ah[mt], bh2[nt]);
            }
            __syncthreads();
        }

        // epilogue 2: relu -> st staging
#pragma unroll
        for (int mt = 0; mt < 4; mt++) {
            int rl = wm2 * 64 + mt * 16 + g;
#pragma unroll
            for (int nt = 0; nt < 2; nt++) {
                int cl = wn2 * 16 + nt * 8 + 2 * tq;
#pragma unroll
                for (int half = 0; half < 2; half++) {
                    int r = rl + 8 * half;
                    st[r * 129 + cl] = fmaxf(acc2[mt][nt][2 * half] + be1[cl], 0.f);
                    st[r * 129 + cl + 1] = fmaxf(acc2[mt][nt][2 * half + 1] + be1[cl + 1], 0.f);
                }
            }
        }
        __syncthreads();

        // credit head: 16 warps x 8 rows
        float wv[4];
#pragma unroll
        for (int i = 0; i < 4; i++) wv[i] = We2[lane + 32 * i];
        float hbv = be2[0];
        float fv = fin[bb];
#pragma unroll
        for (int rr = w * 8; rr < w * 8 + 8; rr++) {
            float s = 0.f;
#pragma unroll
            for (int i = 0; i < 4; i++) s += wv[i] * st[rr * 129 + lane + 32 * i];
#pragma unroll
            for (int o = 16; o; o >>= 1) s += __shfl_xor_sync(0xFFFFFFFFu, s, o);
            if (lane == 0)
                credit[row0 + rr] = fv - (s + hbv);
        }
    }
}

// ---------------- attention (R11 proven: 256 thr, m32n16, hoisted Q) -------------
#define ES_PITCH 1048
#define ATTN_SMEM (32768 + 4096 + 32*ES_PITCH*2 + 1024 + 128)
__global__ void __launch_bounds__(256) attn_mma() {
    extern __shared__ char smem[];
    char* Kst = smem;
    char* Qh = smem + 32768;
    __half* Es = (__half*)(Qh + 4096);
    float* rpart = (float*)(smem + 32768 + 4096 + 32 * ES_PITCH * 2); // [8][32]
    float* rden = rpart + 256;

    int t = threadIdx.x, w = t >> 5, lane = t & 31;
    int qt = blockIdx.x & 31;
    int bh = blockIdx.x >> 5;
    int b = bh >> 2, h = bh & 3;
    int q0 = qt * 32;
    int wn = w;
    int g = lane >> 2, tq = lane & 3;

    uint32_t kbase = smem_u32(Kst);
    uint32_t qbase = smem_u32(Qh);

    {
        int row = t >> 3, ch = t & 7;
        const __nv_bfloat16* sh = g_qkh + (size_t)(b * S + q0 + row) * 512 + h * DH + ch * 8;
        uint32_t d = (uint32_t)((row * 8 + (ch ^ (row & 7))) * 16);
        *(uint4*)(Qh + d) = *(const uint4*)sh;
    }

    auto load_K = [&](int stage, int kt) {
        uint32_t sbk = kbase + stage * 16384;
#pragma unroll
        for (int i = 0; i < 4; i++) {
            int c = t + i * 256;
            int j = c >> 3, ch = c & 7;
            uint32_t d = (uint32_t)((j * 8 + (ch ^ (j & 7))) * 16);
            size_t src = (size_t)(b * S + kt * 128 + j) * 512 + 256 + h * DH + ch * 8;
            cpa16(sbk + d, g_qkh + src);
        }
    };

    load_K(0, 0);
    cpa_commit();
    __syncthreads();

    uint32_t aq[2][4][4];
#pragma unroll
    for (int mt = 0; mt < 2; mt++)
#pragma unroll
        for (int d16 = 0; d16 < 4; d16++) {
            int row = mt * 16 + (lane & 15);
            int ch = d16 * 2 + (lane >> 4);
            uint32_t off = (uint32_t)((row * 8 + (ch ^ (row & 7))) * 16);
            ldm_x4(aq[mt][d16], qbase + off);
        }

    float rsum[4] = {0.f, 0.f, 0.f, 0.f};

    for (int kt = 0; kt < 8; kt++) {
        int stg = kt & 1;
        if (kt < 7) { load_K(stg ^ 1, kt + 1); cpa_commit(); cpa_wait1(); }
        else cpa_wait0();
        __syncthreads();
        uint32_t sbk = kbase + stg * 16384;

        float acc[2][2][4];
#pragma unroll
        for (int mt = 0; mt < 2; mt++)
#pragma unroll
            for (int nt = 0; nt < 2; nt++)
#pragma unroll
                for (int r = 0; r < 4; r++) acc[mt][nt][r] = 0.f;

#pragma unroll
        for (int d16 = 0; d16 < 4; d16++) {
            int j = wn * 16 + (lane & 7) + 8 * (lane >> 4);
            int ch = d16 * 2 + ((lane >> 3) & 1);
            uint32_t off = (uint32_t)((j * 8 + (ch ^ (j & 7))) * 16);
            uint32_t r4[4];
            ldm_x4(r4, sbk + off);
            uint32_t bh2[2][2];
            bh2[0][0] = r4[0]; bh2[0][1] = r4[1];
            bh2[1][0] = r4[2]; bh2[1][1] = r4[3];
#pragma unroll
            for (int mt = 0; mt < 2; mt++)
#pragma unroll
                for (int nt = 0; nt < 2; nt++)
                    mma_bf16(acc[mt][nt], aq[mt][d16], bh2[nt]);
        }
#pragma unroll
        for (int mt = 0; mt < 2; mt++)
#pragma unroll
            for (int nt = 0; nt < 2; nt++) {
                int colb = kt * 128 + wn * 16 + nt * 8 + 2 * tq;
                uint32_t e0 = h2_ex2(h2_pack(acc[mt][nt][0], acc[mt][nt][1]));
                uint32_t e1 = h2_ex2(h2_pack(acc[mt][nt][2], acc[mt][nt][3]));
                float2 f0 = h2_unpack(e0);
                float2 f1 = h2_unpack(e1);
                rsum[mt * 2]     += f0.x + f0.y;
                rsum[mt * 2 + 1] += f1.x + f1.y;
                int r0 = mt * 16 + g;
                *(uint32_t*)&Es[r0 * ES_PITCH + colb] = e0;
                *(uint32_t*)&Es[(r0 + 8) * ES_PITCH + colb] = e1;
            }
        __syncthreads();
    }

#pragma unroll
    for (int i = 0; i < 4; i++) {
        rsum[i] += __shfl_xor_sync(0xFFFFFFFFu, rsum[i], 1);
        rsum[i] += __shfl_xor_sync(0xFFFFFFFFu, rsum[i], 2);
    }
    if (tq == 0) {
#pragma unroll
        for (int i = 0; i < 4; i++)
            rpart[w * 32 + i * 8 + g] = rsum[i];
    }
    __syncthreads();
    if (t < 32) {
        float s = 0.f;
#pragma unroll
        for (int ww = 0; ww < 8; ww++) s += rpart[ww * 32 + t];
        rden[t] = 1.f / s;
    }
    __syncthreads();

#pragma unroll
    for (int jj = 0; jj < 2; jj++) {
        int j2 = t + jj * 256;
        float sx = 0.f, sy = 0.f;
#pragma unroll
        for (int r = 0; r < 32; r++) {
            float2 e = __half22float2(((__half2*)(Es + r * ES_PITCH))[j2]);
            float rd = rden[r];
            sx += e.x * rd;
            sy += e.y * rd;
        }
        atomicAdd(&g_awsum[b * S + 2 * j2], sx);
        atomicAdd(&g_awsum[b * S + 2 * j2 + 1], sy);
    }
}

// ---------------- colmean (shfl suffix scan) + parallel base ---------------------
__global__ void __launch_bounds__(1024) colmean_base_k() {
    __shared__ float wtot[32], woff[32], cmb[1024], bacc[4][256];
    int b = blockIdx.x, sc = blockIdx.y, j = threadIdx.x;
    int lane = j & 31, wid = j >> 5;
    float v = g_str[b * S + j];
#pragma unroll
    for (int off = 1; off < 32; off <<= 1) {
        float o = __shfl_down_sync(0xFFFFFFFFu, v, off);
        if (lane + off < 32) v += o;
    }
    if (lane == 0) wtot[wid] = v;
    __syncthreads();
    if (j < 32) {
        float wv = wtot[j];
        float sv = wv;
#pragma unroll
        for (int off = 1; off < 32; off <<= 1) {
            float o = __shfl_down_sync(0xFFFFFFFFu, sv, off);
            if (lane + off < 32) sv += o;
        }
        woff[j] = sv - wv;
    }
    __syncthreads();
    float suf = v + woff[wid];
    float awm = g_awsum[b * S + j] * (1.f / (NH * S));
    float cmv = awm * suf * (1.f / S);
    if (sc == 0) {
        g_awm[b * S + j] = awm;
        g_colmean[b * S + j] = cmv;
    }
    cmb[j] = cmv;
    __syncthreads();
    int h = j & 255, sg = j >> 8;
    const __nv_bfloat16* xb = g_xh + (size_t)b * S * H;
    int sbeg = sc * 128 + sg * 32;
    float a = 0.f;
    for (int s = sbeg; s < sbeg + 32; s++)
        a += __bfloat162float(xb[(size_t)s * H + h]) * cmb[s];
    bacc[sg][h] = a;
    __syncthreads();
    if (j < 256)
        atomicAdd(&g_base[b * H + j],
                  (bacc[0][j] + bacc[1][j] + bacc[2][j] + bacc[3][j]) * (1.f / S));
}

// ---------------- launch ----------------
extern "C" void kernel_launch(void* const* d_in, const int* in_sizes, int n_in,
                              void* d_out, int out_size) {
    const float* x    = (const float*)d_in[0];
    const float* fin  = (const float*)d_in[1];
    const float* Wq   = (const float*)d_in[3];
    const float* bq   = (const float*)d_in[4];
    const float* Wk   = (const float*)d_in[5];
    const float* bk   = (const float*)d_in[6];
    const float* Wm1  = (const float*)d_in[7];
    const float* bm1  = (const float*)d_in[8];
    const float* Wm2  = (const float*)d_in[9];
    const float* bm2  = (const float*)d_in[10];
    const float* Wi1  = (const float*)d_in[11];
    const float* bi1  = (const float*)d_in[12];
    const float* Wi2  = (const float*)d_in[13];
    const float* bi2  = (const float*)d_in[14];
    const float* We1  = (const float*)d_in[15];
    const float* be1  = (const float*)d_in[16];
    const float* We2  = (const float*)d_in[17];
    const float* be2  = (const float*)d_in[18];
    float* out = (float*)d_out;

    __nv_bfloat16 *pxh, *pWi2T, *pWe1T, *pi1b;
    cudaGetSymbolAddress((void**)&pxh, g_xh);
    cudaGetSymbolAddress((void**)&pWi2T, g_Wi2T);
    cudaGetSymbolAddress((void**)&pWe1T, g_We1T);
    cudaGetSymbolAddress((void**)&pi1b, g_i1b);

    const int SM_HEAD = 66048;
    cudaFuncSetAttribute(gemm_qkmi, cudaFuncAttributeMaxDynamicSharedMemorySize, SM_HEAD);
    cudaFuncSetAttribute(gemm_fe, cudaFuncAttributeMaxDynamicSharedMemorySize, FE_SMEM);
    cudaFuncSetAttribute(attn_mma, cudaFuncAttributeMaxDynamicSharedMemorySize, ATTN_SMEM);

    // 1. prep
    prep_k<<<5456, 256>>>(x, Wq, Wk, Wm1, Wi1, Wi2, We1);

    // 2. merged QK | strengths | I1
    gemm_qkmi<<<dim3(7,128), 256, SM_HEAD>>>(pxh, bq, bk, bm1, bi1, Wm2, bm2);

    // 3. attention column sums
    attn_mma<<<B*NH*32, 256, ATTN_SMEM>>>();

    // 4. colmean (shfl scan) + base
    colmean_base_k<<<dim3(B,8), 1024>>>();

    // 5. fused I2 -> feats -> E1 -> credit, plus cm writers
    gemm_fe<<<384, 512, FE_SMEM>>>(pi1b, pWi2T, pWe1T, bi2, be1,
                                   We2, be2, fin, out, out + B*S);
}

// round 14
// speedup vs baseline: 1.0514x; 1.0016x over previous
#include <cuda_runtime.h>
#include <cuda_bf16.h>
#include <cuda_fp16.h>
#include <math.h>
#include <stdint.h>

#define B 16
#define S 1024
#define H 256
#define NH 4
#define DH 64
#define H2 128
#define MROWS (B*S)   // 16384
#define CEXP (0.125f * 1.44269504f)

// ---------------- scratch (static device globals) ----------------
__device__ __align__(16) __nv_bfloat16 g_xh[MROWS*H];
__device__ __align__(16) __nv_bfloat16 g_WqkT[512*H];
__device__ __align__(16) __nv_bfloat16 g_WmiT[384*H];
__device__ __align__(16) __nv_bfloat16 g_Wi2T[H*H];
__device__ __align__(16) __nv_bfloat16 g_We1T[H2*H];
__device__ __align__(16) __nv_bfloat16 g_qkh[MROWS*512];
__device__ __align__(16) __nv_bfloat16 g_i1b[MROWS*H];
__device__ float g_str[B*S];
__device__ float g_awsum[B*S];

// ---------------- PTX helpers ----------------
__device__ __forceinline__ uint32_t smem_u32(const void* p) {
    return (uint32_t)__cvta_generic_to_shared(p);
}
__device__ __forceinline__ void ldm_x4(uint32_t* r, uint32_t a) {
    asm volatile("ldmatrix.sync.aligned.m8n8.x4.shared.b16 {%0,%1,%2,%3}, [%4];"
        : "=r"(r[0]), "=r"(r[1]), "=r"(r[2]), "=r"(r[3]) : "r"(a));
}
__device__ __forceinline__ void mma_bf16(float* c, const uint32_t* a, const uint32_t* b) {
    asm volatile(
        "mma.sync.aligned.m16n8k16.row.col.f32.bf16.bf16.f32 "
        "{%0,%1,%2,%3},{%4,%5,%6,%7},{%8,%9},{%0,%1,%2,%3};"
        : "+f"(c[0]), "+f"(c[1]), "+f"(c[2]), "+f"(c[3])
        : "r"(a[0]), "r"(a[1]), "r"(a[2]), "r"(a[3]), "r"(b[0]), "r"(b[1]));
}
__device__ __forceinline__ void cpa16(uint32_t dst, const void* src) {
    asm volatile("cp.async.cg.shared.global [%0], [%1], 16;" :: "r"(dst), "l"(src));
}
__device__ __forceinline__ void cpa_commit() { asm volatile("cp.async.commit_group;"); }
__device__ __forceinline__ void cpa_wait1() { asm volatile("cp.async.wait_group 1;"); }
__device__ __forceinline__ void cpa_wait0() { asm volatile("cp.async.wait_group 0;"); }

__device__ __forceinline__ uint32_t h2_ex2(uint32_t x) {
    uint32_t r; asm("ex2.approx.f16x2 %0, %1;" : "=r"(r) : "r"(x)); return r;
}
__device__ __forceinline__ uint32_t h2_pack(float a, float b) {
    __half2 h = __floats2half2_rn(a, b);
    return *reinterpret_cast<uint32_t*>(&h);
}
__device__ __forceinline__ float2 h2_unpack(uint32_t u) {
    return __half22float2(*reinterpret_cast<__half2*>(&u));
}

// ---------------- fused prep ----------------
__global__ void prep_k(const float* __restrict__ x,
                       const float* __restrict__ Wq, const float* __restrict__ Wk,
                       const float* __restrict__ Wm1, const float* __restrict__ Wi1,
                       const float* __restrict__ Wi2, const float* __restrict__ We1) {
    int bid = blockIdx.x, t = threadIdx.x;
    if (bid < 4096) {
        int i = bid * 1024 + t * 4;
        float4 v = *(const float4*)(x + i);
        __nv_bfloat162* dst = (__nv_bfloat162*)(g_xh + i);
        dst[0] = __floats2bfloat162_rn(v.x, v.y);
        dst[1] = __floats2bfloat162_rn(v.z, v.w);
        return;
    }
    bid -= 4096;
    if (bid < 256) {
        int o = bid * 256 + t; int n = o >> 8, k = o & 255;
        g_WqkT[o] = __float2bfloat16(Wq[k * 256 + n]);
        return;
    }
    bid -= 256;
    if (bid < 256) {
        int o = bid * 256 + t; int n = o >> 8, k = o & 255;
        g_WqkT[65536 + o] = __float2bfloat16(Wk[k * 256 + n]);
        return;
    }
    bid -= 256;
    if (bid < 128) {
        int o = bid * 256 + t; int n = o >> 8, k = o & 255;
        g_WmiT[o] = __float2bfloat16(Wm1[k * 128 + n]);
        return;
    }
    bid -= 128;
    if (bid < 256) {
        int o = bid * 256 + t; int n = o >> 8, k = o & 255;
        g_WmiT[128 * 256 + o] = __float2bfloat16(Wi1[k * 256 + n]);
        return;
    }
    bid -= 256;
    if (bid < 256) {
        int o = bid * 256 + t; int n = o >> 8, k = o & 255;
        g_Wi2T[o] = __float2bfloat16(Wi2[k * 256 + n]);
        return;
    }
    bid -= 256;
    if (bid < 128) {
        int o = bid * 256 + t; int n = o >> 8, k = o & 255;
        g_We1T[o] = __float2bfloat16(We1[k * 128 + n]);
        return;
    }
    bid -= 128;
    g_awsum[bid * 256 + t] = 0.f;       // 64 blocks
}

// ---------------- shared GEMM pipeline body (256-thr, 128x128 tile) --------------
__device__ __forceinline__ void gemm_core(
    const __nv_bfloat16* __restrict__ Ah, const __nv_bfloat16* __restrict__ Bt,
    int row0, uint32_t sbase, int t, int wm, int wn, int lane,
    float acc[4][4][4])
{
    const int STB = 16384;
    auto load_stage = [&](int stage, int kt) {
        uint32_t sb = sbase + stage * STB;
#pragma unroll
        for (int i = 0; i < 2; i++) {
            int c = t + i * 256;
            int row = c >> 2, ch = c & 3;
            uint32_t d = (uint32_t)((row * 4 + (ch ^ ((row >> 1) & 3))) * 16);
            cpa16(sb + d, Ah + (size_t)(row0 + row) * 256 + kt * 32 + ch * 8);
            cpa16(sb + 8192 + d, Bt + (size_t)row * 256 + kt * 32 + ch * 8);
        }
    };
    load_stage(0, 0);
    cpa_commit();
    for (int kt = 0; kt < 8; kt++) {
        int st = kt & 1;
        if (kt < 7) { load_stage(st ^ 1, kt + 1); cpa_commit(); cpa_wait1(); }
        else cpa_wait0();
        __syncthreads();
        uint32_t sb = sbase + st * STB;
#pragma unroll
        for (int kk = 0; kk < 2; kk++) {
            uint32_t ah[4][4];
#pragma unroll
            for (int mt = 0; mt < 4; mt++) {
                int row = wm * 64 + mt * 16 + (lane & 15);
                int ch = kk * 2 + (lane >> 4);
                uint32_t off = (uint32_t)((row * 4 + (ch ^ ((row >> 1) & 3))) * 16);
                ldm_x4(ah[mt], sb + off);
            }
            uint32_t bh[4][2];
#pragma unroll
            for (int p = 0; p < 2; p++) {
                int row = wn * 32 + p * 16 + (lane & 7) + 8 * (lane >> 4);
                int ch = kk * 2 + ((lane >> 3) & 1);
                uint32_t off = (uint32_t)((row * 4 + (ch ^ ((row >> 1) & 3))) * 16);
                uint32_t r4[4];
                ldm_x4(r4, sb + 8192 + off);
                bh[2 * p][0] = r4[0]; bh[2 * p][1] = r4[1];
                bh[2 * p + 1][0] = r4[2]; bh[2 * p + 1][1] = r4[3];
            }
#pragma unroll
            for (int mt = 0; mt < 4; mt++)
#pragma unroll
                for (int nt = 0; nt < 4; nt++)
                    mma_bf16(acc[mt][nt], ah[mt], bh[nt]);
        }
        __syncthreads();
    }
}

// ---------------- merged QK | M1(strengths) | I1 GEMM ----------------------------
__global__ void __launch_bounds__(256) gemm_qkmi(
    const __nv_bfloat16* __restrict__ Ah,
    const float* __restrict__ bq, const float* __restrict__ bk,
    const float* __restrict__ bm1, const float* __restrict__ bi1,
    const float* __restrict__ Wm2, const float* __restrict__ bm2)
{
    extern __shared__ char smem[];
    int t = threadIdx.x, w = t >> 5, lane = t & 31;
    int bx = blockIdx.x;
    int row0 = blockIdx.y * 128;
    int wm = w & 1, wn = w >> 1;
    int g = lane >> 2, tq = lane & 3;

    const __nv_bfloat16* Bt = (bx < 4) ? (g_WqkT + (size_t)bx * 128 * 256)
                                       : (g_WmiT + (size_t)(bx - 4) * 128 * 256);

    float acc[4][4][4];
#pragma unroll
    for (int mt = 0; mt < 4; mt++)
#pragma unroll
        for (int nt = 0; nt < 4; nt++)
#pragma unroll
            for (int r = 0; r < 4; r++) acc[mt][nt][r] = 0.f;

    gemm_core(Ah, Bt, row0, smem_u32(smem), t, wm, wn, lane, acc);

    bool head = (bx == 4);
    float* st = (float*)smem;

#pragma unroll
    for (int mt = 0; mt < 4; mt++) {
        int rl = wm * 64 + mt * 16 + g;
#pragma unroll
        for (int nt = 0; nt < 4; nt++) {
            int cl = wn * 32 + nt * 8 + 2 * tq;
#pragma unroll
            for (int half = 0; half < 2; half++) {
                int rr = row0 + rl + 8 * half;
                float v0 = acc[mt][nt][2 * half];
                float v1 = acc[mt][nt][2 * half + 1];
                if (bx < 4) {
                    int gcol = bx * 128 + cl;
                    bool isk = (gcol >= 256);
                    v0 += isk ? bk[gcol - 256] : bq[gcol];
                    v1 += isk ? bk[gcol - 255] : bq[gcol + 1];
                    if (!isk) { v0 *= CEXP; v1 *= CEXP; }
                    *(__nv_bfloat162*)(g_qkh + (size_t)rr * 512 + gcol) =
                        __floats2bfloat162_rn(v0, v1);
                } else if (head) {
                    v0 = fmaxf(v0 + bm1[cl], 0.f);
                    v1 = fmaxf(v1 + bm1[cl + 1], 0.f);
                    st[(rl + 8 * half) * 129 + cl] = v0;
                    st[(rl + 8 * half) * 129 + cl + 1] = v1;
                } else {
                    int c2 = (bx - 5) * 128 + cl;
                    v0 = fmaxf(v0 + bi1[c2], 0.f);
                    v1 = fmaxf(v1 + bi1[c2 + 1], 0.f);
                    *(__nv_bfloat162*)(g_i1b + (size_t)rr * 256 + c2) =
                        __floats2bfloat162_rn(v0, v1);
                }
            }
        }
    }

    if (head) {
        __syncthreads();
        float wv[4];
#pragma unroll
        for (int i = 0; i < 4; i++) wv[i] = Wm2[lane + 32 * i];
        float hbv = bm2[0];
#pragma unroll
        for (int rr = w * 16; rr < w * 16 + 16; rr++) {
            float s = 0.f;
#pragma unroll
            for (int i = 0; i < 4; i++) s += wv[i] * st[rr * 129 + lane + 32 * i];
#pragma unroll
            for (int o = 16; o; o >>= 1) s += __shfl_xor_sync(0xFFFFFFFFu, s, o);
            if (lane == 0)
                g_str[row0 + rr] = 1.f / (1.f + __expf(-(s + hbv)));
        }
    }
}

// ---------------- fused colmean/base -> I2 -> feats -> E1 -> credit + cm ---------
// 1-D grid: bx<128 -> GEMM chain for rows bx*128..+128; bx>=128 -> cm writer.
// smem: PH1 stages [0,49152) | feats 8x8KB [49152,114688) | B2 [114688,131072) |
//       st/scratch [131072, 131072+66048)
#define FE_SMEM (49152 + 65536 + 16384 + 66048)
__device__ __forceinline__ uint32_t feats_off(int r, int c) {  // c even
    return (uint32_t)(49152 + (c >> 5) * 8192 +
                      (r * 4 + (((c >> 3) & 3) ^ ((r >> 1) & 3))) * 16 + (c & 7) * 2);
}
__global__ void __launch_bounds__(512) gemm_fe(
    const __nv_bfloat16* __restrict__ Ah,        // i1b
    const __nv_bfloat16* __restrict__ Bt1,       // Wi2T [256,256]
    const __nv_bfloat16* __restrict__ Bt2,       // We1T [128,256]
    const float* __restrict__ bi2, const float* __restrict__ be1,
    const float* __restrict__ We2, const float* __restrict__ be2,
    const float* __restrict__ fin,
    float* __restrict__ credit, float* __restrict__ cmout)
{
    extern __shared__ char smem[];
    int t = threadIdx.x, w = t >> 5, lane = t & 31;
    const float CA = 1.f / (NH * S);

    if (blockIdx.x >= 128) {       // cm writer: 256 blocks x 64 rows
        int blk = blockIdx.x - 128;
        int j4 = t & 255;
        int rh = t >> 8;
        for (int r = rh * 32; r < rh * 32 + 32; r++) {
            int bi = blk * 64 + r;
            int b = bi >> 10, i = bi & 1023;
            float cstv = g_str[bi] * CA;
            float4 a = ((const float4*)(g_awsum + b * S))[j4];
            int j = j4 * 4;
            float4 v;
            v.x = (i >= j)     ? a.x * cstv : 0.f;
            v.y = (i >= j + 1) ? a.y * cstv : 0.f;
            v.z = (i >= j + 2) ? a.z * cstv : 0.f;
            v.w = (i >= j + 3) ? a.w * cstv : 0.f;
            ((float4*)(cmout + (size_t)bi * S))[j4] = v;
        }
        return;
    }

    int row0 = blockIdx.x * 128;
    int bb = row0 >> 10;
    int g = lane >> 2, tq = lane & 3;
    uint32_t sbase = smem_u32(smem);

    // scratch in the st region (free until epilogue-2)
    float* cmb    = (float*)(smem + 131072);   // [1024]
    float* base_s = cmb + 1024;                // [256]
    float* bacc   = base_s + 256;              // [16][256]
    float* wt     = bacc + 4096;               // [16]
    float* woff   = wt + 16;                   // [17]

    // ---- issue phase-1 stage-0 loads (overlap with prologue) ----
    {
        {   // A: 512 chunks
            int c = t;
            int row = c >> 2, ch = c & 3;
            uint32_t d = (uint32_t)((row * 4 + (ch ^ ((row >> 1) & 3))) * 16);
            cpa16(sbase + d, Ah + (size_t)(row0 + row) * 256 + ch * 8);
        }
#pragma unroll
        for (int i = 0; i < 2; i++) {  // B: 1024 chunks
            int c = t + i * 512;
            int row = c >> 2, ch = c & 3;
            uint32_t d = (uint32_t)((row * 4 + (ch ^ ((row >> 1) & 3))) * 16);
            cpa16(sbase + 8192 + d, Bt1 + (size_t)row * 256 + ch * 8);
        }
        cpa_commit();
    }

    // ---- prologue: colmean (suffix scan of str) + base, block-local ----
    {
        int wd = w;    // 0..15
        float totalU;
        // upper half [512,1024)
        {
            float v = g_str[bb * S + 512 + t];
#pragma unroll
            for (int off = 1; off < 32; off <<= 1) {
                float o = __shfl_down_sync(0xFFFFFFFFu, v, off);
                if (lane + off < 32) v += o;
            }
            if (lane == 0) wt[wd] = v;
            __syncthreads();
            if (t < 16) {
                float w0 = wt[t], sv = w0;
#pragma unroll
                for (int off = 1; off < 16; off <<= 1) {
                    float o = __shfl_down_sync(0x0000FFFFu, sv, off);
                    if (t + off < 16) sv += o;
                }
                woff[t] = sv - w0;
                if (t == 0) woff[16] = sv;
            }
            __syncthreads();
            float suf = v + woff[wd];
            cmb[512 + t] = g_awsum[bb * S + 512 + t] * CA * suf * (1.f / S);
            totalU = woff[16];
            __syncthreads();          // before reusing wt/woff
        }
        // lower half [0,512)
        {
            float v = g_str[bb * S + t];
#pragma unroll
            for (int off = 1; off < 32; off <<= 1) {
                float o = __shfl_down_sync(0xFFFFFFFFu, v, off);
                if (lane + off < 32) v += o;
            }
            if (lane == 0) wt[wd] = v;
            __syncthreads();
            if (t < 16) {
                float w0 = wt[t], sv = w0;
#pragma unroll
                for (int off = 1; off < 16; off <<= 1) {
                    float o = __shfl_down_sync(0x0000FFFFu, sv, off);
                    if (t + off < 16) sv += o;
                }
                woff[t] = sv - w0;
            }
            __syncthreads();
            float suf = v + woff[wd] + totalU;
            cmb[t] = g_awsum[bb * S + t] * CA * suf * (1.f / S);
        }
        __syncthreads();
        // base: oct = t&31 (8 h each), sg = t>>5 (64 s each)
        {
            int oct = t & 31, sg = t >> 5;
            float a[8];
#pragma unroll
            for (int i = 0; i < 8; i++) a[i] = 0.f;
            const __nv_bfloat16* xb = g_xh + (size_t)bb * S * H + oct * 8;
            for (int s = sg * 64; s < sg * 64 + 64; s++) {
                float c = cmb[s];
                uint4 pk = *(const uint4*)(xb + (size_t)s * H);
                const __nv_bfloat162* p2 = (const __nv_bfloat162*)&pk;
#pragma unroll
                for (int i = 0; i < 4; i++) {
                    float2 f = __bfloat1622float2(p2[i]);
                    a[2 * i]     += f.x * c;
                    a[2 * i + 1] += f.y * c;
                }
            }
#pragma unroll
            for (int i = 0; i < 8; i++) bacc[sg * 256 + oct * 8 + i] = a[i];
        }
        __syncthreads();
        if (t < 256) {
            float s = 0.f;
#pragma unroll
            for (int sg = 0; sg < 16; sg++) s += bacc[sg * 256 + t];
            base_s[t] = s * (1.f / S);
        }
        __syncthreads();
    }

    // ---- phase 1: d2 = i1[row0:+128,:] @ Wi2T  (tile 128x256, K=256) ----
    {
        int wm = w & 1, wn = w >> 1;
        const int STB = 24576;
        auto load_stage = [&](int stage, int kt) {
            uint32_t sb = sbase + stage * STB;
            {
                int c = t;
                int row = c >> 2, ch = c & 3;
                uint32_t d = (uint32_t)((row * 4 + (ch ^ ((row >> 1) & 3))) * 16);
                cpa16(sb + d, Ah + (size_t)(row0 + row) * 256 + kt * 32 + ch * 8);
            }
#pragma unroll
            for (int i = 0; i < 2; i++) {
                int c = t + i * 512;
                int row = c >> 2, ch = c & 3;
                uint32_t d = (uint32_t)((row * 4 + (ch ^ ((row >> 1) & 3))) * 16);
                cpa16(sb + 8192 + d, Bt1 + (size_t)row * 256 + kt * 32 + ch * 8);
            }
        };
        float acc[4][4][4];
#pragma unroll
        for (int mt = 0; mt < 4; mt++)
#pragma unroll
            for (int nt = 0; nt < 4; nt++)
#pragma unroll
                for (int r = 0; r < 4; r++) acc[mt][nt][r] = 0.f;

        for (int kt = 0; kt < 8; kt++) {
            int st = kt & 1;
            if (kt < 7) { load_stage(st ^ 1, kt + 1); cpa_commit(); cpa_wait1(); }
            else cpa_wait0();
            __syncthreads();
            uint32_t sb = sbase + st * STB;
#pragma unroll
            for (int kk = 0; kk < 2; kk++) {
                uint32_t ah[4][4];
#pragma unroll
                for (int mt = 0; mt < 4; mt++) {
                    int row = wm * 64 + mt * 16 + (lane & 15);
                    int ch = kk * 2 + (lane >> 4);
                    uint32_t off = (uint32_t)((row * 4 + (ch ^ ((row >> 1) & 3))) * 16);
                    ldm_x4(ah[mt], sb + off);
                }
                uint32_t bh[4][2];
#pragma unroll
                for (int p = 0; p < 2; p++) {
                    int row = wn * 32 + p * 16 + (lane & 7) + 8 * (lane >> 4);
                    int ch = kk * 2 + ((lane >> 3) & 1);
                    uint32_t off = (uint32_t)((row * 4 + (ch ^ ((row >> 1) & 3))) * 16);
                    uint32_t r4[4];
                    ldm_x4(r4, sb + 8192 + off);
                    bh[2 * p][0] = r4[0]; bh[2 * p][1] = r4[1];
                    bh[2 * p + 1][0] = r4[2]; bh[2 * p + 1][1] = r4[3];
                }
#pragma unroll
                for (int mt = 0; mt < 4; mt++)
#pragma unroll
                    for (int nt = 0; nt < 4; nt++)
                        mma_bf16(acc[mt][nt], ah[mt], bh[nt]);
            }
            __syncthreads();
        }

        // prefetch phase-2 B stage 0 (overlaps epilogue)
        {
            int c = t;
            int row = c >> 2, ch = c & 3;
            uint32_t d = (uint32_t)((row * 4 + (ch ^ ((row >> 1) & 3))) * 16);
            cpa16(sbase + 114688 + d, Bt2 + (size_t)row * 256 + ch * 8);
        }
        cpa_commit();

        // epilogue 1: feats -> smem (bf16, chunked swizzled layout)
        int rb = row0 & 1023;
#pragma unroll
        for (int mt = 0; mt < 4; mt++) {
            int rl = wm * 64 + mt * 16 + g;
#pragma unroll
            for (int nt = 0; nt < 4; nt++) {
                int cl = wn * 32 + nt * 8 + 2 * tq;
#pragma unroll
                for (int half = 0; half < 2; half++) {
                    int r = rl + 8 * half;
                    float v0 = 0.1f * tanhf(acc[mt][nt][2 * half] + bi2[cl]);
                    float v1 = 0.1f * tanhf(acc[mt][nt][2 * half + 1] + bi2[cl + 1]);
                    float cmv = cmb[rb + r] * (1.f / S);
                    float f0 = base_s[cl] + v0 * cmv;
                    float f1 = base_s[cl + 1] + v1 * cmv;
                    *(__nv_bfloat162*)(smem + feats_off(r, cl)) =
                        __floats2bfloat162_rn(f0, f1);
                }
            }
        }
    }

    // ---- phase 2: o1 = relu(feats @ We1T + be1); credit head ----
    float* st = (float*)(smem + 131072);
    {
        int wm2 = w & 1, wn2 = w >> 1;
        auto load_B2 = [&](int stage, int kt) {
            uint32_t sb = sbase + 114688 + stage * 8192;
            int c = t;
            int row = c >> 2, ch = c & 3;
            uint32_t d = (uint32_t)((row * 4 + (ch ^ ((row >> 1) & 3))) * 16);
            cpa16(sb + d, Bt2 + (size_t)row * 256 + kt * 32 + ch * 8);
        };
        float acc2[4][2][4];
#pragma unroll
        for (int mt = 0; mt < 4; mt++)
#pragma unroll
            for (int nt = 0; nt < 2; nt++)
#pragma unroll
                for (int r = 0; r < 4; r++) acc2[mt][nt][r] = 0.f;

        for (int kt = 0; kt < 8; kt++) {
            int st2 = kt & 1;
            if (kt < 7) { load_B2(st2 ^ 1, kt + 1); cpa_commit(); cpa_wait1(); }
            else cpa_wait0();
            __syncthreads();
            uint32_t ab = sbase + 49152 + kt * 8192;
            uint32_t bbse = sbase + 114688 + st2 * 8192;
#pragma unroll
            for (int kk = 0; kk < 2; kk++) {
                uint32_t ah[4][4];
#pragma unroll
                for (int mt = 0; mt < 4; mt++) {
                    int row = wm2 * 64 + mt * 16 + (lane & 15);
                    int ch = kk * 2 + (lane >> 4);
                    uint32_t off = (uint32_t)((row * 4 + (ch ^ ((row >> 1) & 3))) * 16);
                    ldm_x4(ah[mt], ab + off);
                }
                uint32_t bh2[2][2];
                {
                    int row = wn2 * 16 + (lane & 7) + 8 * (lane >> 4);
                    int ch = kk * 2 + ((lane >> 3) & 1);
                    uint32_t off = (uint32_t)((row * 4 + (ch ^ ((row >> 1) & 3))) * 16);
                    uint32_t r4[4];
                    ldm_x4(r4, bbse + off);
                    bh2[0][0] = r4[0]; bh2[0][1] = r4[1];
                    bh2[1][0] = r4[2]; bh2[1][1] = r4[3];
                }
#pragma unroll
                for (int mt = 0; mt < 4; mt++)
#pragma unroll
                    for (int nt = 0; nt < 2; nt++)
                        mma_bf16(acc2[mt][nt], ah[mt], bh2[nt]);
            }
            __syncthreads();
        }

        // epilogue 2: relu -> st staging
#pragma unroll
        for (int mt = 0; mt < 4; mt++) {
            int rl = wm2 * 64 + mt * 16 + g;
#pragma unroll
            for (int nt = 0; nt < 2; nt++) {
                int cl = wn2 * 16 + nt * 8 + 2 * tq;
#pragma unroll
                for (int half = 0; half < 2; half++) {
                    int r = rl + 8 * half;
                    st[r * 129 + cl] = fmaxf(acc2[mt][nt][2 * half] + be1[cl], 0.f);
                    st[r * 129 + cl + 1] = fmaxf(acc2[mt][nt][2 * half + 1] + be1[cl + 1], 0.f);
                }
            }
        }
        __syncthreads();

        // credit head: 16 warps x 8 rows
        float wv[4];
#pragma unroll
        for (int i = 0; i < 4; i++) wv[i] = We2[lane + 32 * i];
        float hbv = be2[0];
        float fv = fin[bb];
#pragma unroll
        for (int rr = w * 8; rr < w * 8 + 8; rr++) {
            float s = 0.f;
#pragma unroll
            for (int i = 0; i < 4; i++) s += wv[i] * st[rr * 129 + lane + 32 * i];
#pragma unroll
            for (int o = 16; o; o >>= 1) s += __shfl_xor_sync(0xFFFFFFFFu, s, o);
            if (lane == 0)
                credit[row0 + rr] = fv - (s + hbv);
        }
    }
}

// ---------------- attention (256 thr, m32n16, hoisted Q) -------------------------
#define ES_PITCH 1048
#define ATTN_SMEM (32768 + 4096 + 32*ES_PITCH*2 + 1024 + 128)
__global__ void __launch_bounds__(256) attn_mma() {
    extern __shared__ char smem[];
    char* Kst = smem;
    char* Qh = smem + 32768;
    __half* Es = (__half*)(Qh + 4096);
    float* rpart = (float*)(smem + 32768 + 4096 + 32 * ES_PITCH * 2);
    float* rden = rpart + 256;

    int t = threadIdx.x, w = t >> 5, lane = t & 31;
    int qt = blockIdx.x & 31;
    int bh = blockIdx.x >> 5;
    int b = bh >> 2, h = bh & 3;
    int q0 = qt * 32;
    int wn = w;
    int g = lane >> 2, tq = lane & 3;

    uint32_t kbase = smem_u32(Kst);
    uint32_t qbase = smem_u32(Qh);

    {
        int row = t >> 3, ch = t & 7;
        const __nv_bfloat16* sh = g_qkh + (size_t)(b * S + q0 + row) * 512 + h * DH + ch * 8;
        uint32_t d = (uint32_t)((row * 8 + (ch ^ (row & 7))) * 16);
        *(uint4*)(Qh + d) = *(const uint4*)sh;
    }

    auto load_K = [&](int stage, int kt) {
        uint32_t sbk = kbase + stage * 16384;
#pragma unroll
        for (int i = 0; i < 4; i++) {
            int c = t + i * 256;
            int j = c >> 3, ch = c & 7;
            uint32_t d = (uint32_t)((j * 8 + (ch ^ (j & 7))) * 16);
            size_t src = (size_t)(b * S + kt * 128 + j) * 512 + 256 + h * DH + ch * 8;
            cpa16(sbk + d, g_qkh + src);
        }
    };

    load_K(0, 0);
    cpa_commit();
    __syncthreads();

    uint32_t aq[2][4][4];
#pragma unroll
    for (int mt = 0; mt < 2; mt++)
#pragma unroll
        for (int d16 = 0; d16 < 4; d16++) {
            int row = mt * 16 + (lane & 15);
            int ch = d16 * 2 + (lane >> 4);
            uint32_t off = (uint32_t)((row * 8 + (ch ^ (row & 7))) * 16);
            ldm_x4(aq[mt][d16], qbase + off);
        }

    float rsum[4] = {0.f, 0.f, 0.f, 0.f};

    for (int kt = 0; kt < 8; kt++) {
        int stg = kt & 1;
        if (kt < 7) { load_K(stg ^ 1, kt + 1); cpa_commit(); cpa_wait1(); }
        else cpa_wait0();
        __syncthreads();
        uint32_t sbk = kbase + stg * 16384;

        float acc[2][2][4];
#pragma unroll
        for (int mt = 0; mt < 2; mt++)
#pragma unroll
            for (int nt = 0; nt < 2; nt++)
#pragma unroll
                for (int r = 0; r < 4; r++) acc[mt][nt][r] = 0.f;

#pragma unroll
        for (int d16 = 0; d16 < 4; d16++) {
            int j = wn * 16 + (lane & 7) + 8 * (lane >> 4);
            int ch = d16 * 2 + ((lane >> 3) & 1);
            uint32_t off = (uint32_t)((j * 8 + (ch ^ (j & 7))) * 16);
            uint32_t r4[4];
            ldm_x4(r4, sbk + off);
            uint32_t bh2[2][2];
            bh2[0][0] = r4[0]; bh2[0][1] = r4[1];
            bh2[1][0] = r4[2]; bh2[1][1] = r4[3];
#pragma unroll
            for (int mt = 0; mt < 2; mt++)
#pragma unroll
                for (int nt = 0; nt < 2; nt++)
                    mma_bf16(acc[mt][nt], aq[mt][d16], bh2[nt]);
        }
#pragma unroll
        for (int mt = 0; mt < 2; mt++)
#pragma unroll
            for (int nt = 0; nt < 2; nt++) {
                int colb = kt * 128 + wn * 16 + nt * 8 + 2 * tq;
                uint32_t e0 = h2_ex2(h2_pack(acc[mt][nt][0], acc[mt][nt][1]));
                uint32_t e1 = h2_ex2(h2_pack(acc[mt][nt][2], acc[mt][nt][3]));
                float2 f0 = h2_unpack(e0);
                float2 f1 = h2_unpack(e1);
                rsum[mt * 2]     += f0.x + f0.y;
                rsum[mt * 2 + 1] += f1.x + f1.y;
                int r0 = mt * 16 + g;
                *(uint32_t*)&Es[r0 * ES_PITCH + colb] = e0;
                *(uint32_t*)&Es[(r0 + 8) * ES_PITCH + colb] = e1;
            }
        __syncthreads();
    }

#pragma unroll
    for (int i = 0; i < 4; i++) {
        rsum[i] += __shfl_xor_sync(0xFFFFFFFFu, rsum[i], 1);
        rsum[i] += __shfl_xor_sync(0xFFFFFFFFu, rsum[i], 2);
    }
    if (tq == 0) {
#pragma unroll
        for (int i = 0; i < 4; i++)
            rpart[w * 32 + i * 8 + g] = rsum[i];
    }
    __syncthreads();
    if (t < 32) {
        float s = 0.f;
#pragma unroll
        for (int ww = 0; ww < 8; ww++) s += rpart[ww * 32 + t];
        rden[t] = 1.f / s;
    }
    __syncthreads();

#pragma unroll
    for (int jj = 0; jj < 2; jj++) {
        int j2 = t + jj * 256;
        float sx = 0.f, sy = 0.f;
#pragma unroll
        for (int r = 0; r < 32; r++) {
            float2 e = __half22float2(((__half2*)(Es + r * ES_PITCH))[j2]);
            float rd = rden[r];
            sx += e.x * rd;
            sy += e.y * rd;
        }
        atomicAdd(&g_awsum[b * S + 2 * j2], sx);
        atomicAdd(&g_awsum[b * S + 2 * j2 + 1], sy);
    }
}

// ---------------- launch ----------------
extern "C" void kernel_launch(void* const* d_in, const int* in_sizes, int n_in,
                              void* d_out, int out_size) {
    const float* x    = (const float*)d_in[0];
    const float* fin  = (const float*)d_in[1];
    const float* Wq   = (const float*)d_in[3];
    const float* bq   = (const float*)d_in[4];
    const float* Wk   = (const float*)d_in[5];
    const float* bk   = (const float*)d_in[6];
    const float* Wm1  = (const float*)d_in[7];
    const float* bm1  = (const float*)d_in[8];
    const float* Wm2  = (const float*)d_in[9];
    const float* bm2  = (const float*)d_in[10];
    const float* Wi1  = (const float*)d_in[11];
    const float* bi1  = (const float*)d_in[12];
    const float* Wi2  = (const float*)d_in[13];
    const float* bi2  = (const float*)d_in[14];
    const float* We1  = (const float*)d_in[15];
    const float* be1  = (const float*)d_in[16];
    const float* We2  = (const float*)d_in[17];
    const float* be2  = (const float*)d_in[18];
    float* out = (float*)d_out;

    __nv_bfloat16 *pxh, *pWi2T, *pWe1T, *pi1b;
    cudaGetSymbolAddress((void**)&pxh, g_xh);
    cudaGetSymbolAddress((void**)&pWi2T, g_Wi2T);
    cudaGetSymbolAddress((void**)&pWe1T, g_We1T);
    cudaGetSymbolAddress((void**)&pi1b, g_i1b);

    const int SM_HEAD = 66048;
    cudaFuncSetAttribute(gemm_qkmi, cudaFuncAttributeMaxDynamicSharedMemorySize, SM_HEAD);
    cudaFuncSetAttribute(gemm_fe, cudaFuncAttributeMaxDynamicSharedMemorySize, FE_SMEM);
    cudaFuncSetAttribute(attn_mma, cudaFuncAttributeMaxDynamicSharedMemorySize, ATTN_SMEM);

    // 1. prep
    prep_k<<<5440, 256>>>(x, Wq, Wk, Wm1, Wi1, Wi2, We1);

    // 2. merged QK | strengths | I1
    gemm_qkmi<<<dim3(7,128), 256, SM_HEAD>>>(pxh, bq, bk, bm1, bi1, Wm2, bm2);

    // 3. attention column sums
    attn_mma<<<B*NH*32, 256, ATTN_SMEM>>>();

    // 4. fused colmean/base -> I2 -> feats -> E1 -> credit, plus cm writers
    gemm_fe<<<384, 512, FE_SMEM>>>(pi1b, pWi2T, pWe1T, bi2, be1,
                                   We2, be2, fin, out, out + B*S);
}